// round 12
// baseline (speedup 1.0000x reference)
#include <cuda_runtime.h>
#include <cuda_fp16.h>
#include <cstdint>
#include <math.h>

// Problem dims (fixed)
#define H_DIM 4096
#define I_DIM 11008
#define NTOK  4096

#define BKH 128                         // halves (k) per pipeline stage (256B rows)
#define S  2
#define LDSTR 136                       // halves per smem row (256B data + 16B pad; 272B = 17*16B)
#define TILE128 (128 * LDSTR)
#define TILE256 (256 * LDSTR)
#define NTHREADS 512

// Device scratch — natural K-major fp16 layouts
__device__ __half g_x[(size_t)NTOK * H_DIM];
__device__ __half g_h[(size_t)NTOK * I_DIM];
__device__ __half g_wu[(size_t)I_DIM * H_DIM];
__device__ __half g_wg[(size_t)I_DIM * H_DIM];
__device__ __half g_wd[(size_t)H_DIM * I_DIM];
__device__ int    g_idx[NTOK];
__device__ int    g_zidx[NTOK];
__device__ int    g_count;

// ---------------------------------------------------------------------------
__device__ __forceinline__ uint32_t h2_as_u32(__half2 h) {
    return *reinterpret_cast<uint32_t*>(&h);
}
__device__ __forceinline__ void cp16(void* dst_smem, const void* src) {
    uint32_t d = (uint32_t)__cvta_generic_to_shared(dst_smem);
    asm volatile("cp.async.cg.shared.global [%0], [%1], 16;" :: "r"(d), "l"(src) : "memory");
}
#define CP_COMMIT() asm volatile("cp.async.commit_group;" ::: "memory")
#define CP_WAIT(n)  asm volatile("cp.async.wait_group %0;" :: "n"(n) : "memory")

__device__ __forceinline__ void mma16(float* d, const uint32_t* a, const uint32_t* b) {
    asm volatile(
        "mma.sync.aligned.m16n8k16.row.col.f32.f16.f16.f32 "
        "{%0,%1,%2,%3}, {%4,%5,%6,%7}, {%8,%9}, {%0,%1,%2,%3};"
        : "+f"(d[0]), "+f"(d[1]), "+f"(d[2]), "+f"(d[3])
        : "r"(a[0]), "r"(a[1]), "r"(a[2]), "r"(a[3]), "r"(b[0]), "r"(b[1]));
}
__device__ __forceinline__ void ldsm4(uint32_t addr, uint32_t* r) {
    asm volatile("ldmatrix.sync.aligned.m8n8.x4.shared.b16 {%0,%1,%2,%3}, [%4];"
                 : "=r"(r[0]), "=r"(r[1]), "=r"(r[2]), "=r"(r[3]) : "r"(addr));
}

// ---------------------------------------------------------------------------
// Compaction scan (single block): active list + inactive list
// ---------------------------------------------------------------------------
__global__ void compact_kernel(const int* __restrict__ mask) {
    __shared__ int warp_sums[32];
    const int tid = threadIdx.x, lane = tid & 31, warp = tid >> 5;
    int flags[4], cnt = 0;
#pragma unroll
    for (int j = 0; j < 4; ++j) {
        int f = (mask[tid * 4 + j] != 0) ? 1 : 0;
        flags[j] = f; cnt += f;
    }
    int v = cnt;
#pragma unroll
    for (int o = 1; o < 32; o <<= 1) { int n = __shfl_up_sync(~0u, v, o); if (lane >= o) v += n; }
    if (lane == 31) warp_sums[warp] = v;
    __syncthreads();
    if (warp == 0) {
        int s = warp_sums[lane];
#pragma unroll
        for (int o = 1; o < 32; o <<= 1) { int n = __shfl_up_sync(~0u, s, o); if (lane >= o) s += n; }
        warp_sums[lane] = s;
    }
    __syncthreads();
    int base = v - cnt + (warp > 0 ? warp_sums[warp - 1] : 0);
#pragma unroll
    for (int j = 0; j < 4; ++j) {
        int t = tid * 4 + j;
        if (flags[j]) g_idx[base++] = t;
        else          g_zidx[t - base] = t;
    }
    if (tid == 1023) g_count = base;
}

// ---------------------------------------------------------------------------
__device__ __forceinline__ uint4 cvt8(float4 f0, float4 f1) {
    uint4 o;
    o.x = h2_as_u32(__floats2half2_rn(f0.x, f0.y));
    o.y = h2_as_u32(__floats2half2_rn(f0.z, f0.w));
    o.z = h2_as_u32(__floats2half2_rn(f1.x, f1.y));
    o.w = h2_as_u32(__floats2half2_rn(f1.z, f1.w));
    return o;
}

// One launch converts all three weight matrices.
__global__ void cvt3_kernel(const float4* __restrict__ s0, uint4* __restrict__ d0,
                            const float4* __restrict__ s1, uint4* __restrict__ d1,
                            const float4* __restrict__ s2, uint4* __restrict__ d2,
                            int ngroups) {
    int i = blockIdx.x * blockDim.x + threadIdx.x;
    int stride = gridDim.x * blockDim.x;
    const int total = 3 * ngroups;
    for (; i < total; i += stride) {
        int sel = i / ngroups;
        int k = i - sel * ngroups;
        const float4* s = (sel == 0) ? s0 : (sel == 1) ? s1 : s2;
        uint4* d = (sel == 0) ? d0 : (sel == 1) ? d1 : d2;
        d[k] = cvt8(s[2 * k], s[2 * k + 1]);
    }
}

// Gather active rows into g_x (fp16); zero-pad to 128-row boundary.
__global__ void gather_kernel(const float4* __restrict__ hidden) {
    int row = blockIdx.x;
    int c = g_count;
    int cpad = (c + 127) & ~127;
    if (row >= cpad) return;
    uint4* dst = (uint4*)(g_x + (size_t)row * H_DIM);
    if (row < c) {
        const float4* src = hidden + (size_t)g_idx[row] * (H_DIM / 4);
        for (int i = threadIdx.x; i < H_DIM / 8; i += 256)
            dst[i] = cvt8(src[2 * i], src[2 * i + 1]);
    } else {
        uint4 z = make_uint4(0, 0, 0, 0);
        for (int i = threadIdx.x; i < H_DIM / 8; i += 256) dst[i] = z;
    }
}

__global__ void zero_rows_kernel(float4* __restrict__ out) {
    int nz = NTOK - g_count;
    if ((int)blockIdx.x >= nz) return;
    float4* p = out + (size_t)g_zidx[blockIdx.x] * (H_DIM / 4);
    float4 z = make_float4(0.f, 0.f, 0.f, 0.f);
    for (int i = threadIdx.x; i < H_DIM / 4; i += 256) p[i] = z;
}

// ---------------------------------------------------------------------------
// Fused up+gate GEMM. Block 128x128, 16 warps @ 32x32 (4m x 4n), dual acc.
// BKH=128 halves/stage (8 k-groups), S=2, per-warp kg skew over 8.
// ---------------------------------------------------------------------------
#define STG_F (3 * TILE128)   // halves per stage

__global__ __launch_bounds__(NTHREADS, 1)
void fused_upgate_kernel()
{
    const int Mc = g_count;
    const int m0 = blockIdx.x * 128;
    if (m0 >= Mc) return;
    const int n0 = blockIdx.y * 128;

    extern __shared__ __half smh[];
    const uint32_t smem_b = (uint32_t)__cvta_generic_to_shared(smh);

    const int tid  = threadIdx.x;
    const int lane = tid & 31;
    const int wid  = tid >> 5;      // 0..15
    const int wm   = wid >> 2;      // 0..3
    const int wn   = wid & 3;       // 0..3
    const int g    = lane >> 2;
    const int c    = lane & 3;
    const int skew = wid & 7;

    const int nk = H_DIM / BKH;     // 32

    uint32_t a_off[2], u_off[2], gg_off[2];
    {
        const int ar = wm * 32 + ((lane >> 3) & 1) * 8 + (lane & 7);
        const int ac = ((lane >> 4) & 1) * 8;
#pragma unroll
        for (int i = 0; i < 2; ++i) a_off[i] = (uint32_t)((ar + i * 16) * LDSTR + ac);
        const int br = wn * 32 + ((lane >> 4) & 1) * 8 + (lane & 7);
        const int bc = ((lane >> 3) & 1) * 8;
#pragma unroll
        for (int p = 0; p < 2; ++p) {
            u_off[p]  = (uint32_t)(TILE128     + (br + p * 16) * LDSTR + bc);
            gg_off[p] = (uint32_t)(2 * TILE128 + (br + p * 16) * LDSTR + bc);
        }
    }

    const __half* srcA = g_x  + (size_t)m0 * H_DIM;
    const __half* srcU = g_wu + (size_t)n0 * H_DIM;
    const __half* srcG = g_wg + (size_t)n0 * H_DIM;

    // per stage: 128 rows x 256B per matrix; 512 threads x 16B chunks:
    // 16 chunks per row, tid covers 32 rows per pass -> 4 passes per matrix
#define ISSUE_F(t) do {                                                        \
        __half* st = smh + ((t) % S) * STG_F;                                  \
        const size_t kof = (size_t)(t) * BKH;                                  \
        _Pragma("unroll")                                                      \
        for (int ii = 0; ii < 4; ++ii) {                                       \
            int id = tid + ii * 512;                                           \
            int row = id >> 4, ch = id & 15;                                   \
            cp16(st + row * LDSTR + ch * 8,                                    \
                 srcA + (size_t)row * H_DIM + kof + ch * 8);                   \
            cp16(st + TILE128 + row * LDSTR + ch * 8,                          \
                 srcU + (size_t)row * H_DIM + kof + ch * 8);                   \
            cp16(st + 2 * TILE128 + row * LDSTR + ch * 8,                      \
                 srcG + (size_t)row * H_DIM + kof + ch * 8);                   \
        }                                                                      \
    } while (0)

#pragma unroll
    for (int t = 0; t < S - 1; ++t) { ISSUE_F(t); CP_COMMIT(); }

    float acc_u[2][4][4], acc_g[2][4][4];
#pragma unroll
    for (int i = 0; i < 2; ++i)
#pragma unroll
        for (int j = 0; j < 4; ++j)
#pragma unroll
            for (int r = 0; r < 4; ++r) { acc_u[i][j][r] = 0.f; acc_g[i][j][r] = 0.f; }

    for (int t = 0; t < nk; ++t) {
        CP_WAIT(S - 2);
        __syncthreads();
        if (t + S - 1 < nk) ISSUE_F(t + S - 1);
        CP_COMMIT();

        const uint32_t sb = smem_b + (uint32_t)((t % S) * STG_F) * 2;

#pragma unroll
        for (int kgi = 0; kgi < 8; ++kgi) {
            const int kg = (kgi + skew) & 7;   // per-warp phase skew
            const uint32_t kb = (uint32_t)kg * 32;
            uint32_t af[2][4], uf[4][2], gf[4][2];
#pragma unroll
            for (int i = 0; i < 2; ++i) ldsm4(sb + 2 * a_off[i] + kb, af[i]);
#pragma unroll
            for (int p = 0; p < 2; ++p) {
                uint32_t ru[4], rg[4];
                ldsm4(sb + 2 * u_off[p] + kb, ru);
                ldsm4(sb + 2 * gg_off[p] + kb, rg);
                uf[2 * p][0] = ru[0]; uf[2 * p][1] = ru[1];
                uf[2 * p + 1][0] = ru[2]; uf[2 * p + 1][1] = ru[3];
                gf[2 * p][0] = rg[0]; gf[2 * p][1] = rg[1];
                gf[2 * p + 1][0] = rg[2]; gf[2 * p + 1][1] = rg[3];
            }
#pragma unroll
            for (int i = 0; i < 2; ++i)
#pragma unroll
                for (int j = 0; j < 4; ++j) {
                    mma16(acc_u[i][j], af[i], uf[j]);
                    mma16(acc_g[i][j], af[i], gf[j]);
                }
        }
    }
#undef ISSUE_F

    // epilogue: h = up*silu(gate) -> fp16
#pragma unroll
    for (int i = 0; i < 2; ++i) {
#pragma unroll
        for (int h = 0; h < 2; ++h) {
            const int gm = m0 + wm * 32 + i * 16 + g + h * 8;
            __half* rowp = g_h + (size_t)gm * I_DIM;
#pragma unroll
            for (int j = 0; j < 4; ++j) {
                const int gn = n0 + wn * 32 + j * 8 + 2 * c;
                float u0 = acc_u[i][j][h * 2 + 0], u1 = acc_u[i][j][h * 2 + 1];
                float gg0 = acc_g[i][j][h * 2 + 0], gg1 = acc_g[i][j][h * 2 + 1];
                float h0 = u0 * (gg0 / (1.f + __expf(-gg0)));
                float h1 = u1 * (gg1 / (1.f + __expf(-gg1)));
                *(__half2*)(rowp + gn) = __floats2half2_rn(h0, h1);
            }
        }
    }
}

// ---------------------------------------------------------------------------
// Down GEMM. Block 256x128, 16 warps @ 64x32 (4m x 4n), BKH=128, S=2, skew.
// ---------------------------------------------------------------------------
#define STG_D (TILE256 + TILE128)

__global__ __launch_bounds__(NTHREADS, 1)
void down_kernel(float* __restrict__ out)
{
    const int Mc = g_count;
    const int m0 = blockIdx.x * 256;
    if (m0 >= Mc) return;
    const int n0 = blockIdx.y * 128;

    extern __shared__ __half smh[];
    const uint32_t smem_b = (uint32_t)__cvta_generic_to_shared(smh);

    const int tid  = threadIdx.x;
    const int lane = tid & 31;
    const int wid  = tid >> 5;
    const int wm   = wid >> 2;      // 0..3
    const int wn   = wid & 3;       // 0..3
    const int g    = lane >> 2;
    const int c    = lane & 3;
    const int skew = wid & 7;

    const int nk = I_DIM / BKH;     // 86

    uint32_t a_off[4], b_off[2];
    {
        const int ar = wm * 64 + ((lane >> 3) & 1) * 8 + (lane & 7);
        const int ac = ((lane >> 4) & 1) * 8;
#pragma unroll
        for (int i = 0; i < 4; ++i) a_off[i] = (uint32_t)((ar + i * 16) * LDSTR + ac);
        const int br = wn * 32 + ((lane >> 4) & 1) * 8 + (lane & 7);
        const int bc = ((lane >> 3) & 1) * 8;
#pragma unroll
        for (int p = 0; p < 2; ++p)
            b_off[p] = (uint32_t)(TILE256 + (br + p * 16) * LDSTR + bc);
    }

    const __half* srcA = g_h  + (size_t)m0 * I_DIM;
    const __half* srcB = g_wd + (size_t)n0 * I_DIM;

    // A: 256 rows x 16 chunks = 4096 chunks -> 8 passes; B: 128 rows -> 4 passes
#define ISSUE_D(t) do {                                                        \
        __half* st = smh + ((t) % S) * STG_D;                                  \
        const size_t kof = (size_t)(t) * BKH;                                  \
        _Pragma("unroll")                                                      \
        for (int ii = 0; ii < 8; ++ii) {                                       \
            int id = tid + ii * 512;                                           \
            int row = id >> 4, ch = id & 15;                                   \
            cp16(st + row * LDSTR + ch * 8,                                    \
                 srcA + (size_t)row * I_DIM + kof + ch * 8);                   \
        }                                                                      \
        _Pragma("unroll")                                                      \
        for (int ii = 0; ii < 4; ++ii) {                                       \
            int id = tid + ii * 512;                                           \
            int row = id >> 4, ch = id & 15;                                   \
            cp16(st + TILE256 + row * LDSTR + ch * 8,                          \
                 srcB + (size_t)row * I_DIM + kof + ch * 8);                   \
        }                                                                      \
    } while (0)

#pragma unroll
    for (int t = 0; t < S - 1; ++t) { ISSUE_D(t); CP_COMMIT(); }

    float acc[4][4][4];
#pragma unroll
    for (int i = 0; i < 4; ++i)
#pragma unroll
        for (int j = 0; j < 4; ++j)
#pragma unroll
            for (int r = 0; r < 4; ++r) acc[i][j][r] = 0.f;

    for (int t = 0; t < nk; ++t) {
        CP_WAIT(S - 2);
        __syncthreads();
        if (t + S - 1 < nk) ISSUE_D(t + S - 1);
        CP_COMMIT();

        const uint32_t sb = smem_b + (uint32_t)((t % S) * STG_D) * 2;

#pragma unroll
        for (int kgi = 0; kgi < 8; ++kgi) {
            const int kg = (kgi + skew) & 7;
            const uint32_t kb = (uint32_t)kg * 32;
            uint32_t af[4][4], bf[4][2];
#pragma unroll
            for (int i = 0; i < 4; ++i) ldsm4(sb + 2 * a_off[i] + kb, af[i]);
#pragma unroll
            for (int p = 0; p < 2; ++p) {
                uint32_t rb[4];
                ldsm4(sb + 2 * b_off[p] + kb, rb);
                bf[2 * p][0] = rb[0]; bf[2 * p][1] = rb[1];
                bf[2 * p + 1][0] = rb[2]; bf[2 * p + 1][1] = rb[3];
            }
#pragma unroll
            for (int i = 0; i < 4; ++i)
#pragma unroll
                for (int j = 0; j < 4; ++j)
                    mma16(acc[i][j], af[i], bf[j]);
        }
    }
#undef ISSUE_D

    // epilogue: scatter
#pragma unroll
    for (int i = 0; i < 4; ++i) {
#pragma unroll
        for (int h = 0; h < 2; ++h) {
            const int gm = m0 + wm * 64 + i * 16 + g + h * 8;
            if (gm < Mc) {
                float* rowp = out + (size_t)g_idx[gm] * H_DIM;
#pragma unroll
                for (int j = 0; j < 4; ++j) {
                    const int gn = n0 + wn * 32 + j * 8 + c * 2;
                    *(float2*)(rowp + gn) =
                        make_float2(acc[i][j][h * 2 + 0], acc[i][j][h * 2 + 1]);
                }
            }
        }
    }
}

// ---------------------------------------------------------------------------
extern "C" void kernel_launch(void* const* d_in, const int* in_sizes, int n_in,
                              void* d_out, int out_size)
{
    const float* hidden = (const float*)d_in[0];
    const float* w_up   = (const float*)d_in[1];
    const float* w_gate = (const float*)d_in[2];
    const float* w_down = (const float*)d_in[3];
    const int*   mask   = (const int*)d_in[4];
    float* out = (float*)d_out;

    const int SMEM_F = S * STG_F * sizeof(__half);   // 208896
    const int SMEM_D = S * STG_D * sizeof(__half);   // 208896
    cudaFuncSetAttribute(fused_upgate_kernel, cudaFuncAttributeMaxDynamicSharedMemorySize, SMEM_F);
    cudaFuncSetAttribute(down_kernel,         cudaFuncAttributeMaxDynamicSharedMemorySize, SMEM_D);

    void *d_wu, *d_wg, *d_wd;
    cudaGetSymbolAddress(&d_wu, g_wu);
    cudaGetSymbolAddress(&d_wg, g_wg);
    cudaGetSymbolAddress(&d_wd, g_wd);

    compact_kernel<<<1, 1024>>>(mask);
    gather_kernel<<<NTOK, 256>>>((const float4*)hidden);

    const int wg_groups = (I_DIM * H_DIM) / 8;
    cvt3_kernel<<<8192, 256>>>((const float4*)w_up,   (uint4*)d_wu,
                               (const float4*)w_gate, (uint4*)d_wg,
                               (const float4*)w_down, (uint4*)d_wd, wg_groups);

    zero_rows_kernel<<<NTOK, 256>>>((float4*)out);

    dim3 blk(NTHREADS);
    fused_upgate_kernel<<<dim3(NTOK / 128, I_DIM / 128), blk, SMEM_F>>>();
    down_kernel<<<dim3(NTOK / 256, H_DIM / 128), blk, SMEM_D>>>(out);
}

// round 13
// speedup vs baseline: 1.0266x; 1.0266x over previous
#include <cuda_runtime.h>
#include <cuda_fp16.h>
#include <cstdint>
#include <math.h>

// Problem dims (fixed)
#define H_DIM 4096
#define I_DIM 11008
#define NTOK  4096

#define BKH 64                          // halves (k) per pipeline stage
#define S  4
#define LDSTR 72                        // halves per smem row (128B data + 16B pad)
#define TILE128 (128 * LDSTR)
#define TILE256 (256 * LDSTR)
#define NTHREADS 512

// Device scratch — natural K-major fp16 layouts
__device__ __half g_x[(size_t)NTOK * H_DIM];
__device__ __half g_h[(size_t)NTOK * I_DIM];
__device__ __half g_wu[(size_t)I_DIM * H_DIM];
__device__ __half g_wg[(size_t)I_DIM * H_DIM];
__device__ __half g_wd[(size_t)H_DIM * I_DIM];
__device__ int    g_idx[NTOK];
__device__ int    g_zidx[NTOK];
__device__ int    g_count;

// ---------------------------------------------------------------------------
// Side stream + events, created once at static init (host-side resources only;
// no device memory, no per-call behavior change).
// ---------------------------------------------------------------------------
struct AuxStreams {
    cudaStream_t side;
    cudaEvent_t ev_fork, ev_wuwg, ev_side_done;
    AuxStreams() {
        cudaStreamCreateWithFlags(&side, cudaStreamNonBlocking);
        cudaEventCreateWithFlags(&ev_fork, cudaEventDisableTiming);
        cudaEventCreateWithFlags(&ev_wuwg, cudaEventDisableTiming);
        cudaEventCreateWithFlags(&ev_side_done, cudaEventDisableTiming);
    }
};
static AuxStreams g_aux;

// ---------------------------------------------------------------------------
__device__ __forceinline__ uint32_t h2_as_u32(__half2 h) {
    return *reinterpret_cast<uint32_t*>(&h);
}
__device__ __forceinline__ void cp16(void* dst_smem, const void* src) {
    uint32_t d = (uint32_t)__cvta_generic_to_shared(dst_smem);
    asm volatile("cp.async.cg.shared.global [%0], [%1], 16;" :: "r"(d), "l"(src) : "memory");
}
#define CP_COMMIT() asm volatile("cp.async.commit_group;" ::: "memory")
#define CP_WAIT(n)  asm volatile("cp.async.wait_group %0;" :: "n"(n) : "memory")

__device__ __forceinline__ void mma16(float* d, const uint32_t* a, const uint32_t* b) {
    asm volatile(
        "mma.sync.aligned.m16n8k16.row.col.f32.f16.f16.f32 "
        "{%0,%1,%2,%3}, {%4,%5,%6,%7}, {%8,%9}, {%0,%1,%2,%3};"
        : "+f"(d[0]), "+f"(d[1]), "+f"(d[2]), "+f"(d[3])
        : "r"(a[0]), "r"(a[1]), "r"(a[2]), "r"(a[3]), "r"(b[0]), "r"(b[1]));
}
__device__ __forceinline__ void ldsm4(uint32_t addr, uint32_t* r) {
    asm volatile("ldmatrix.sync.aligned.m8n8.x4.shared.b16 {%0,%1,%2,%3}, [%4];"
                 : "=r"(r[0]), "=r"(r[1]), "=r"(r[2]), "=r"(r[3]) : "r"(addr));
}

// ---------------------------------------------------------------------------
// Compaction scan (single block): active list + inactive list
// ---------------------------------------------------------------------------
__global__ void compact_kernel(const int* __restrict__ mask) {
    __shared__ int warp_sums[32];
    const int tid = threadIdx.x, lane = tid & 31, warp = tid >> 5;
    int flags[4], cnt = 0;
#pragma unroll
    for (int j = 0; j < 4; ++j) {
        int f = (mask[tid * 4 + j] != 0) ? 1 : 0;
        flags[j] = f; cnt += f;
    }
    int v = cnt;
#pragma unroll
    for (int o = 1; o < 32; o <<= 1) { int n = __shfl_up_sync(~0u, v, o); if (lane >= o) v += n; }
    if (lane == 31) warp_sums[warp] = v;
    __syncthreads();
    if (warp == 0) {
        int s = warp_sums[lane];
#pragma unroll
        for (int o = 1; o < 32; o <<= 1) { int n = __shfl_up_sync(~0u, s, o); if (lane >= o) s += n; }
        warp_sums[lane] = s;
    }
    __syncthreads();
    int base = v - cnt + (warp > 0 ? warp_sums[warp - 1] : 0);
#pragma unroll
    for (int j = 0; j < 4; ++j) {
        int t = tid * 4 + j;
        if (flags[j]) g_idx[base++] = t;
        else          g_zidx[t - base] = t;
    }
    if (tid == 1023) g_count = base;
}

// ---------------------------------------------------------------------------
__device__ __forceinline__ uint4 cvt8(float4 f0, float4 f1) {
    uint4 o;
    o.x = h2_as_u32(__floats2half2_rn(f0.x, f0.y));
    o.y = h2_as_u32(__floats2half2_rn(f0.z, f0.w));
    o.z = h2_as_u32(__floats2half2_rn(f1.x, f1.y));
    o.w = h2_as_u32(__floats2half2_rn(f1.z, f1.w));
    return o;
}

__global__ void cvt_kernel(const float4* __restrict__ src, uint4* __restrict__ dst, int ngroups) {
    int i = blockIdx.x * blockDim.x + threadIdx.x;
    int stride = gridDim.x * blockDim.x;
    for (; i < ngroups; i += stride) dst[i] = cvt8(src[2 * i], src[2 * i + 1]);
}

// Gather active rows into g_x (fp16); zero-pad to 128-row boundary.
__global__ void gather_kernel(const float4* __restrict__ hidden) {
    int row = blockIdx.x;
    int c = g_count;
    int cpad = (c + 127) & ~127;
    if (row >= cpad) return;
    uint4* dst = (uint4*)(g_x + (size_t)row * H_DIM);
    if (row < c) {
        const float4* src = hidden + (size_t)g_idx[row] * (H_DIM / 4);
        for (int i = threadIdx.x; i < H_DIM / 8; i += 256)
            dst[i] = cvt8(src[2 * i], src[2 * i + 1]);
    } else {
        uint4 z = make_uint4(0, 0, 0, 0);
        for (int i = threadIdx.x; i < H_DIM / 8; i += 256) dst[i] = z;
    }
}

__global__ void zero_rows_kernel(float4* __restrict__ out) {
    int nz = NTOK - g_count;
    if ((int)blockIdx.x >= nz) return;
    float4* p = out + (size_t)g_zidx[blockIdx.x] * (H_DIM / 4);
    float4 z = make_float4(0.f, 0.f, 0.f, 0.f);
    for (int i = threadIdx.x; i < H_DIM / 4; i += 256) p[i] = z;
}

// ---------------------------------------------------------------------------
// Fused up+gate GEMM. Block 128x128, 16 warps @ 32x32 (4m x 4n), dual acc.
// Per-warp kg skew. (Round-11 config — best measured.)
// ---------------------------------------------------------------------------
#define STG_F (3 * TILE128)   // halves per stage

__global__ __launch_bounds__(NTHREADS, 1)
void fused_upgate_kernel()
{
    const int Mc = g_count;
    const int m0 = blockIdx.x * 128;
    if (m0 >= Mc) return;
    const int n0 = blockIdx.y * 128;

    extern __shared__ __half smh[];
    const uint32_t smem_b = (uint32_t)__cvta_generic_to_shared(smh);

    const int tid  = threadIdx.x;
    const int lane = tid & 31;
    const int wid  = tid >> 5;      // 0..15
    const int wm   = wid >> 2;      // 0..3
    const int wn   = wid & 3;       // 0..3
    const int g    = lane >> 2;
    const int c    = lane & 3;
    const int skew = wid & 3;

    const int nk = H_DIM / BKH;     // 64

    uint32_t a_off[2], u_off[2], gg_off[2];
    {
        const int ar = wm * 32 + ((lane >> 3) & 1) * 8 + (lane & 7);
        const int ac = ((lane >> 4) & 1) * 8;
#pragma unroll
        for (int i = 0; i < 2; ++i) a_off[i] = (uint32_t)((ar + i * 16) * LDSTR + ac);
        const int br = wn * 32 + ((lane >> 4) & 1) * 8 + (lane & 7);
        const int bc = ((lane >> 3) & 1) * 8;
#pragma unroll
        for (int p = 0; p < 2; ++p) {
            u_off[p]  = (uint32_t)(TILE128     + (br + p * 16) * LDSTR + bc);
            gg_off[p] = (uint32_t)(2 * TILE128 + (br + p * 16) * LDSTR + bc);
        }
    }

    const __half* srcA = g_x  + (size_t)m0 * H_DIM;
    const __half* srcU = g_wu + (size_t)n0 * H_DIM;
    const __half* srcG = g_wg + (size_t)n0 * H_DIM;

#define ISSUE_F(t) do {                                                        \
        __half* st = smh + ((t) % S) * STG_F;                                  \
        const size_t kof = (size_t)(t) * BKH;                                  \
        _Pragma("unroll")                                                      \
        for (int ii = 0; ii < 2; ++ii) {                                       \
            int id = tid + ii * 512;                                           \
            int row = id >> 3, ch = id & 7;                                    \
            cp16(st + row * LDSTR + ch * 8,                                    \
                 srcA + (size_t)row * H_DIM + kof + ch * 8);                   \
            cp16(st + TILE128 + row * LDSTR + ch * 8,                          \
                 srcU + (size_t)row * H_DIM + kof + ch * 8);                   \
            cp16(st + 2 * TILE128 + row * LDSTR + ch * 8,                      \
                 srcG + (size_t)row * H_DIM + kof + ch * 8);                   \
        }                                                                      \
    } while (0)

#pragma unroll
    for (int t = 0; t < S - 1; ++t) { ISSUE_F(t); CP_COMMIT(); }

    float acc_u[2][4][4], acc_g[2][4][4];
#pragma unroll
    for (int i = 0; i < 2; ++i)
#pragma unroll
        for (int j = 0; j < 4; ++j)
#pragma unroll
            for (int r = 0; r < 4; ++r) { acc_u[i][j][r] = 0.f; acc_g[i][j][r] = 0.f; }

    for (int t = 0; t < nk; ++t) {
        CP_WAIT(S - 2);
        __syncthreads();
        if (t + S - 1 < nk) ISSUE_F(t + S - 1);
        CP_COMMIT();

        const uint32_t sb = smem_b + (uint32_t)((t % S) * STG_F) * 2;

#pragma unroll
        for (int kgi = 0; kgi < 4; ++kgi) {
            const int kg = (kgi + skew) & 3;   // per-warp phase skew
            const uint32_t kb = (uint32_t)kg * 32;
            uint32_t af[2][4], uf[4][2], gf[4][2];
#pragma unroll
            for (int i = 0; i < 2; ++i) ldsm4(sb + 2 * a_off[i] + kb, af[i]);
#pragma unroll
            for (int p = 0; p < 2; ++p) {
                uint32_t ru[4], rg[4];
                ldsm4(sb + 2 * u_off[p] + kb, ru);
                ldsm4(sb + 2 * gg_off[p] + kb, rg);
                uf[2 * p][0] = ru[0]; uf[2 * p][1] = ru[1];
                uf[2 * p + 1][0] = ru[2]; uf[2 * p + 1][1] = ru[3];
                gf[2 * p][0] = rg[0]; gf[2 * p][1] = rg[1];
                gf[2 * p + 1][0] = rg[2]; gf[2 * p + 1][1] = rg[3];
            }
#pragma unroll
            for (int i = 0; i < 2; ++i)
#pragma unroll
                for (int j = 0; j < 4; ++j) {
                    mma16(acc_u[i][j], af[i], uf[j]);
                    mma16(acc_g[i][j], af[i], gf[j]);
                }
        }
    }
#undef ISSUE_F

    // epilogue: h = up*silu(gate) -> fp16
#pragma unroll
    for (int i = 0; i < 2; ++i) {
#pragma unroll
        for (int h = 0; h < 2; ++h) {
            const int gm = m0 + wm * 32 + i * 16 + g + h * 8;
            __half* rowp = g_h + (size_t)gm * I_DIM;
#pragma unroll
            for (int j = 0; j < 4; ++j) {
                const int gn = n0 + wn * 32 + j * 8 + 2 * c;
                float u0 = acc_u[i][j][h * 2 + 0], u1 = acc_u[i][j][h * 2 + 1];
                float gg0 = acc_g[i][j][h * 2 + 0], gg1 = acc_g[i][j][h * 2 + 1];
                float h0 = u0 * (gg0 / (1.f + __expf(-gg0)));
                float h1 = u1 * (gg1 / (1.f + __expf(-gg1)));
                *(__half2*)(rowp + gn) = __floats2half2_rn(h0, h1);
            }
        }
    }
}

// ---------------------------------------------------------------------------
// Down GEMM. Block 256x128, 16 warps @ 64x32 (4m x 4n), kg skew.
// ---------------------------------------------------------------------------
#define STG_D (TILE256 + TILE128)

__global__ __launch_bounds__(NTHREADS, 1)
void down_kernel(float* __restrict__ out)
{
    const int Mc = g_count;
    const int m0 = blockIdx.x * 256;
    if (m0 >= Mc) return;
    const int n0 = blockIdx.y * 128;

    extern __shared__ __half smh[];
    const uint32_t smem_b = (uint32_t)__cvta_generic_to_shared(smh);

    const int tid  = threadIdx.x;
    const int lane = tid & 31;
    const int wid  = tid >> 5;
    const int wm   = wid >> 2;      // 0..3
    const int wn   = wid & 3;       // 0..3
    const int g    = lane >> 2;
    const int c    = lane & 3;
    const int skew = wid & 3;

    const int nk = I_DIM / BKH;     // 172

    uint32_t a_off[4], b_off[2];
    {
        const int ar = wm * 64 + ((lane >> 3) & 1) * 8 + (lane & 7);
        const int ac = ((lane >> 4) & 1) * 8;
#pragma unroll
        for (int i = 0; i < 4; ++i) a_off[i] = (uint32_t)((ar + i * 16) * LDSTR + ac);
        const int br = wn * 32 + ((lane >> 4) & 1) * 8 + (lane & 7);
        const int bc = ((lane >> 3) & 1) * 8;
#pragma unroll
        for (int p = 0; p < 2; ++p)
            b_off[p] = (uint32_t)(TILE256 + (br + p * 16) * LDSTR + bc);
    }

    const __half* srcA = g_h  + (size_t)m0 * I_DIM;
    const __half* srcB = g_wd + (size_t)n0 * I_DIM;

#define ISSUE_D(t) do {                                                        \
        __half* st = smh + ((t) % S) * STG_D;                                  \
        const size_t kof = (size_t)(t) * BKH;                                  \
        _Pragma("unroll")                                                      \
        for (int ii = 0; ii < 4; ++ii) {                                       \
            int id = tid + ii * 512;                                           \
            int row = id >> 3, ch = id & 7;                                    \
            cp16(st + row * LDSTR + ch * 8,                                    \
                 srcA + (size_t)row * I_DIM + kof + ch * 8);                   \
        }                                                                      \
        _Pragma("unroll")                                                      \
        for (int ii = 0; ii < 2; ++ii) {                                       \
            int id = tid + ii * 512;                                           \
            int row = id >> 3, ch = id & 7;                                    \
            cp16(st + TILE256 + row * LDSTR + ch * 8,                          \
                 srcB + (size_t)row * I_DIM + kof + ch * 8);                   \
        }                                                                      \
    } while (0)

#pragma unroll
    for (int t = 0; t < S - 1; ++t) { ISSUE_D(t); CP_COMMIT(); }

    float acc[4][4][4];
#pragma unroll
    for (int i = 0; i < 4; ++i)
#pragma unroll
        for (int j = 0; j < 4; ++j)
#pragma unroll
            for (int r = 0; r < 4; ++r) acc[i][j][r] = 0.f;

    for (int t = 0; t < nk; ++t) {
        CP_WAIT(S - 2);
        __syncthreads();
        if (t + S - 1 < nk) ISSUE_D(t + S - 1);
        CP_COMMIT();

        const uint32_t sb = smem_b + (uint32_t)((t % S) * STG_D) * 2;

#pragma unroll
        for (int kgi = 0; kgi < 4; ++kgi) {
            const int kg = (kgi + skew) & 3;
            const uint32_t kb = (uint32_t)kg * 32;
            uint32_t af[4][4], bf[4][2];
#pragma unroll
            for (int i = 0; i < 4; ++i) ldsm4(sb + 2 * a_off[i] + kb, af[i]);
#pragma unroll
            for (int p = 0; p < 2; ++p) {
                uint32_t rb[4];
                ldsm4(sb + 2 * b_off[p] + kb, rb);
                bf[2 * p][0] = rb[0]; bf[2 * p][1] = rb[1];
                bf[2 * p + 1][0] = rb[2]; bf[2 * p + 1][1] = rb[3];
            }
#pragma unroll
            for (int i = 0; i < 4; ++i)
#pragma unroll
                for (int j = 0; j < 4; ++j)
                    mma16(acc[i][j], af[i], bf[j]);
        }
    }
#undef ISSUE_D

    // epilogue: scatter
#pragma unroll
    for (int i = 0; i < 4; ++i) {
#pragma unroll
        for (int h = 0; h < 2; ++h) {
            const int gm = m0 + wm * 64 + i * 16 + g + h * 8;
            if (gm < Mc) {
                float* rowp = out + (size_t)g_idx[gm] * H_DIM;
#pragma unroll
                for (int j = 0; j < 4; ++j) {
                    const int gn = n0 + wn * 32 + j * 8 + c * 2;
                    *(float2*)(rowp + gn) =
                        make_float2(acc[i][j][h * 2 + 0], acc[i][j][h * 2 + 1]);
                }
            }
        }
    }
}

// ---------------------------------------------------------------------------
extern "C" void kernel_launch(void* const* d_in, const int* in_sizes, int n_in,
                              void* d_out, int out_size)
{
    const float* hidden = (const float*)d_in[0];
    const float* w_up   = (const float*)d_in[1];
    const float* w_gate = (const float*)d_in[2];
    const float* w_down = (const float*)d_in[3];
    const int*   mask   = (const int*)d_in[4];
    float* out = (float*)d_out;

    const int SMEM_F = S * STG_F * sizeof(__half);   // 221184
    const int SMEM_D = S * STG_D * sizeof(__half);   // 221184
    cudaFuncSetAttribute(fused_upgate_kernel, cudaFuncAttributeMaxDynamicSharedMemorySize, SMEM_F);
    cudaFuncSetAttribute(down_kernel,         cudaFuncAttributeMaxDynamicSharedMemorySize, SMEM_D);

    void *d_wu, *d_wg, *d_wd;
    cudaGetSymbolAddress(&d_wu, g_wu);
    cudaGetSymbolAddress(&d_wg, g_wg);
    cudaGetSymbolAddress(&d_wd, g_wd);

    const int wg_groups = (I_DIM * H_DIM) / 8;

    // main stream: compact, then fork
    compact_kernel<<<1, 1024>>>(mask);
    cudaEventRecord(g_aux.ev_fork, 0);
    cudaStreamWaitEvent(g_aux.side, g_aux.ev_fork, 0);

    // side stream: weight conversion + output zeroing (overlaps gather & fused GEMM)
    cvt_kernel<<<4096, 256, 0, g_aux.side>>>((const float4*)w_up,   (uint4*)d_wu, wg_groups);
    cvt_kernel<<<4096, 256, 0, g_aux.side>>>((const float4*)w_gate, (uint4*)d_wg, wg_groups);
    cudaEventRecord(g_aux.ev_wuwg, g_aux.side);
    cvt_kernel<<<4096, 256, 0, g_aux.side>>>((const float4*)w_down, (uint4*)d_wd, wg_groups);
    zero_rows_kernel<<<NTOK, 256, 0, g_aux.side>>>((float4*)out);
    cudaEventRecord(g_aux.ev_side_done, g_aux.side);

    // main stream: gather, then GEMMs gated on side-stream progress
    gather_kernel<<<NTOK, 256>>>((const float4*)hidden);

    dim3 blk(NTHREADS);
    cudaStreamWaitEvent(0, g_aux.ev_wuwg, 0);
    fused_upgate_kernel<<<dim3(NTOK / 128, I_DIM / 128), blk, SMEM_F>>>();
    cudaStreamWaitEvent(0, g_aux.ev_side_done, 0);
    down_kernel<<<dim3(NTOK / 256, H_DIM / 128), blk, SMEM_D>>>(out);
}

// round 14
// speedup vs baseline: 1.0652x; 1.0376x over previous
#include <cuda_runtime.h>
#include <cuda_fp16.h>
#include <cstdint>
#include <math.h>

// Problem dims (fixed)
#define H_DIM 4096
#define I_DIM 11008
#define NTOK  4096
#define I_HALF (I_DIM / 2)              // 5504 = 43*128 = 86*64

#define BKH 64                          // halves (k) per pipeline stage
#define S  4
#define LDSTR 72                        // halves per smem row (128B data + 16B pad)
#define TILE128 (128 * LDSTR)
#define TILE256 (256 * LDSTR)
#define NTHREADS 512

// Device scratch — natural K-major fp16 layouts
__device__ __half g_x[(size_t)NTOK * H_DIM];
__device__ __half g_h[(size_t)NTOK * I_DIM];
__device__ __half g_wu[(size_t)I_DIM * H_DIM];
__device__ __half g_wg[(size_t)I_DIM * H_DIM];
__device__ __half g_wd[(size_t)H_DIM * I_DIM];
__device__ int    g_idx[NTOK];
__device__ int    g_zidx[NTOK];
__device__ int    g_count;

// ---------------------------------------------------------------------------
// Side stream + events (host-side only, created once at static init)
// ---------------------------------------------------------------------------
struct AuxStreams {
    cudaStream_t side;
    cudaEvent_t ev_fork, ev_A, ev_B, ev_F0, ev_S;
    AuxStreams() {
        cudaStreamCreateWithFlags(&side, cudaStreamNonBlocking);
        cudaEventCreateWithFlags(&ev_fork, cudaEventDisableTiming);
        cudaEventCreateWithFlags(&ev_A, cudaEventDisableTiming);
        cudaEventCreateWithFlags(&ev_B, cudaEventDisableTiming);
        cudaEventCreateWithFlags(&ev_F0, cudaEventDisableTiming);
        cudaEventCreateWithFlags(&ev_S, cudaEventDisableTiming);
    }
};
static AuxStreams g_aux;

// ---------------------------------------------------------------------------
__device__ __forceinline__ uint32_t h2_as_u32(__half2 h) {
    return *reinterpret_cast<uint32_t*>(&h);
}
__device__ __forceinline__ void cp16(void* dst_smem, const void* src) {
    uint32_t d = (uint32_t)__cvta_generic_to_shared(dst_smem);
    asm volatile("cp.async.cg.shared.global [%0], [%1], 16;" :: "r"(d), "l"(src) : "memory");
}
#define CP_COMMIT() asm volatile("cp.async.commit_group;" ::: "memory")
#define CP_WAIT(n)  asm volatile("cp.async.wait_group %0;" :: "n"(n) : "memory")

__device__ __forceinline__ void mma16(float* d, const uint32_t* a, const uint32_t* b) {
    asm volatile(
        "mma.sync.aligned.m16n8k16.row.col.f32.f16.f16.f32 "
        "{%0,%1,%2,%3}, {%4,%5,%6,%7}, {%8,%9}, {%0,%1,%2,%3};"
        : "+f"(d[0]), "+f"(d[1]), "+f"(d[2]), "+f"(d[3])
        : "r"(a[0]), "r"(a[1]), "r"(a[2]), "r"(a[3]), "r"(b[0]), "r"(b[1]));
}
__device__ __forceinline__ void ldsm4(uint32_t addr, uint32_t* r) {
    asm volatile("ldmatrix.sync.aligned.m8n8.x4.shared.b16 {%0,%1,%2,%3}, [%4];"
                 : "=r"(r[0]), "=r"(r[1]), "=r"(r[2]), "=r"(r[3]) : "r"(addr));
}

// ---------------------------------------------------------------------------
// Compaction scan (single block): active list + inactive list
// ---------------------------------------------------------------------------
__global__ void compact_kernel(const int* __restrict__ mask) {
    __shared__ int warp_sums[32];
    const int tid = threadIdx.x, lane = tid & 31, warp = tid >> 5;
    int flags[4], cnt = 0;
#pragma unroll
    for (int j = 0; j < 4; ++j) {
        int f = (mask[tid * 4 + j] != 0) ? 1 : 0;
        flags[j] = f; cnt += f;
    }
    int v = cnt;
#pragma unroll
    for (int o = 1; o < 32; o <<= 1) { int n = __shfl_up_sync(~0u, v, o); if (lane >= o) v += n; }
    if (lane == 31) warp_sums[warp] = v;
    __syncthreads();
    if (warp == 0) {
        int s = warp_sums[lane];
#pragma unroll
        for (int o = 1; o < 32; o <<= 1) { int n = __shfl_up_sync(~0u, s, o); if (lane >= o) s += n; }
        warp_sums[lane] = s;
    }
    __syncthreads();
    int base = v - cnt + (warp > 0 ? warp_sums[warp - 1] : 0);
#pragma unroll
    for (int j = 0; j < 4; ++j) {
        int t = tid * 4 + j;
        if (flags[j]) g_idx[base++] = t;
        else          g_zidx[t - base] = t;
    }
    if (tid == 1023) g_count = base;
}

// ---------------------------------------------------------------------------
__device__ __forceinline__ uint4 cvt8(float4 f0, float4 f1) {
    uint4 o;
    o.x = h2_as_u32(__floats2half2_rn(f0.x, f0.y));
    o.y = h2_as_u32(__floats2half2_rn(f0.z, f0.w));
    o.z = h2_as_u32(__floats2half2_rn(f1.x, f1.y));
    o.w = h2_as_u32(__floats2half2_rn(f1.z, f1.w));
    return o;
}

__global__ void cvt_kernel(const float4* __restrict__ src, uint4* __restrict__ dst, int ngroups) {
    int i = blockIdx.x * blockDim.x + threadIdx.x;
    int stride = gridDim.x * blockDim.x;
    for (; i < ngroups; i += stride) dst[i] = cvt8(src[2 * i], src[2 * i + 1]);
}

// Gather active rows into g_x (fp16); zero-pad to 128-row boundary.
__global__ void gather_kernel(const float4* __restrict__ hidden) {
    int row = blockIdx.x;
    int c = g_count;
    int cpad = (c + 127) & ~127;
    if (row >= cpad) return;
    uint4* dst = (uint4*)(g_x + (size_t)row * H_DIM);
    if (row < c) {
        const float4* src = hidden + (size_t)g_idx[row] * (H_DIM / 4);
        for (int i = threadIdx.x; i < H_DIM / 8; i += 256)
            dst[i] = cvt8(src[2 * i], src[2 * i + 1]);
    } else {
        uint4 z = make_uint4(0, 0, 0, 0);
        for (int i = threadIdx.x; i < H_DIM / 8; i += 256) dst[i] = z;
    }
}

__global__ void zero_rows_kernel(float4* __restrict__ out) {
    int nz = NTOK - g_count;
    if ((int)blockIdx.x >= nz) return;
    float4* p = out + (size_t)g_zidx[blockIdx.x] * (H_DIM / 4);
    float4 z = make_float4(0.f, 0.f, 0.f, 0.f);
    for (int i = threadIdx.x; i < H_DIM / 4; i += 256) p[i] = z;
}

// ---------------------------------------------------------------------------
// Fused up+gate GEMM. Block 128x128, 16 warps @ 32x32 (4m x 4n), dual acc,
// per-warp kg skew. n_off selects the n-half (in 128-blocks).
// ---------------------------------------------------------------------------
#define STG_F (3 * TILE128)   // halves per stage

__global__ __launch_bounds__(NTHREADS, 1)
void fused_upgate_kernel(int n_off)
{
    const int Mc = g_count;
    const int m0 = blockIdx.x * 128;
    if (m0 >= Mc) return;
    const int n0 = (blockIdx.y + n_off) * 128;

    extern __shared__ __half smh[];
    const uint32_t smem_b = (uint32_t)__cvta_generic_to_shared(smh);

    const int tid  = threadIdx.x;
    const int lane = tid & 31;
    const int wid  = tid >> 5;      // 0..15
    const int wm   = wid >> 2;      // 0..3
    const int wn   = wid & 3;       // 0..3
    const int g    = lane >> 2;
    const int c    = lane & 3;
    const int skew = wid & 3;

    const int nk = H_DIM / BKH;     // 64

    uint32_t a_off[2], u_off[2], gg_off[2];
    {
        const int ar = wm * 32 + ((lane >> 3) & 1) * 8 + (lane & 7);
        const int ac = ((lane >> 4) & 1) * 8;
#pragma unroll
        for (int i = 0; i < 2; ++i) a_off[i] = (uint32_t)((ar + i * 16) * LDSTR + ac);
        const int br = wn * 32 + ((lane >> 4) & 1) * 8 + (lane & 7);
        const int bc = ((lane >> 3) & 1) * 8;
#pragma unroll
        for (int p = 0; p < 2; ++p) {
            u_off[p]  = (uint32_t)(TILE128     + (br + p * 16) * LDSTR + bc);
            gg_off[p] = (uint32_t)(2 * TILE128 + (br + p * 16) * LDSTR + bc);
        }
    }

    const __half* srcA = g_x  + (size_t)m0 * H_DIM;
    const __half* srcU = g_wu + (size_t)n0 * H_DIM;
    const __half* srcG = g_wg + (size_t)n0 * H_DIM;

#define ISSUE_F(t) do {                                                        \
        __half* st = smh + ((t) % S) * STG_F;                                  \
        const size_t kof = (size_t)(t) * BKH;                                  \
        _Pragma("unroll")                                                      \
        for (int ii = 0; ii < 2; ++ii) {                                       \
            int id = tid + ii * 512;                                           \
            int row = id >> 3, ch = id & 7;                                    \
            cp16(st + row * LDSTR + ch * 8,                                    \
                 srcA + (size_t)row * H_DIM + kof + ch * 8);                   \
            cp16(st + TILE128 + row * LDSTR + ch * 8,                          \
                 srcU + (size_t)row * H_DIM + kof + ch * 8);                   \
            cp16(st + 2 * TILE128 + row * LDSTR + ch * 8,                      \
                 srcG + (size_t)row * H_DIM + kof + ch * 8);                   \
        }                                                                      \
    } while (0)

#pragma unroll
    for (int t = 0; t < S - 1; ++t) { ISSUE_F(t); CP_COMMIT(); }

    float acc_u[2][4][4], acc_g[2][4][4];
#pragma unroll
    for (int i = 0; i < 2; ++i)
#pragma unroll
        for (int j = 0; j < 4; ++j)
#pragma unroll
            for (int r = 0; r < 4; ++r) { acc_u[i][j][r] = 0.f; acc_g[i][j][r] = 0.f; }

    for (int t = 0; t < nk; ++t) {
        CP_WAIT(S - 2);
        __syncthreads();
        if (t + S - 1 < nk) ISSUE_F(t + S - 1);
        CP_COMMIT();

        const uint32_t sb = smem_b + (uint32_t)((t % S) * STG_F) * 2;

#pragma unroll
        for (int kgi = 0; kgi < 4; ++kgi) {
            const int kg = (kgi + skew) & 3;
            const uint32_t kb = (uint32_t)kg * 32;
            uint32_t af[2][4], uf[4][2], gf[4][2];
#pragma unroll
            for (int i = 0; i < 2; ++i) ldsm4(sb + 2 * a_off[i] + kb, af[i]);
#pragma unroll
            for (int p = 0; p < 2; ++p) {
                uint32_t ru[4], rg[4];
                ldsm4(sb + 2 * u_off[p] + kb, ru);
                ldsm4(sb + 2 * gg_off[p] + kb, rg);
                uf[2 * p][0] = ru[0]; uf[2 * p][1] = ru[1];
                uf[2 * p + 1][0] = ru[2]; uf[2 * p + 1][1] = ru[3];
                gf[2 * p][0] = rg[0]; gf[2 * p][1] = rg[1];
                gf[2 * p + 1][0] = rg[2]; gf[2 * p + 1][1] = rg[3];
            }
#pragma unroll
            for (int i = 0; i < 2; ++i)
#pragma unroll
                for (int j = 0; j < 4; ++j) {
                    mma16(acc_u[i][j], af[i], uf[j]);
                    mma16(acc_g[i][j], af[i], gf[j]);
                }
        }
    }
#undef ISSUE_F

    // epilogue: h = up*silu(gate) -> fp16
#pragma unroll
    for (int i = 0; i < 2; ++i) {
#pragma unroll
        for (int h = 0; h < 2; ++h) {
            const int gm = m0 + wm * 32 + i * 16 + g + h * 8;
            __half* rowp = g_h + (size_t)gm * I_DIM;
#pragma unroll
            for (int j = 0; j < 4; ++j) {
                const int gn = n0 + wn * 32 + j * 8 + 2 * c;
                float u0 = acc_u[i][j][h * 2 + 0], u1 = acc_u[i][j][h * 2 + 1];
                float gg0 = acc_g[i][j][h * 2 + 0], gg1 = acc_g[i][j][h * 2 + 1];
                float h0 = u0 * (gg0 / (1.f + __expf(-gg0)));
                float h1 = u1 * (gg1 / (1.f + __expf(-gg1)));
                *(__half2*)(rowp + gn) = __floats2half2_rn(h0, h1);
            }
        }
    }
}

// ---------------------------------------------------------------------------
// Down GEMM, split-K. Block 256x128, 16 warps @ 64x32 (4m x 4n), kg skew.
// k_base selects the I half; ACC=0 writes out, ACC=1 accumulates.
// ---------------------------------------------------------------------------
#define STG_D (TILE256 + TILE128)

template <int ACC>
__global__ __launch_bounds__(NTHREADS, 1)
void down_kernel(float* __restrict__ out, int k_base)
{
    const int Mc = g_count;
    const int m0 = blockIdx.x * 256;
    if (m0 >= Mc) return;
    const int n0 = blockIdx.y * 128;

    extern __shared__ __half smh[];
    const uint32_t smem_b = (uint32_t)__cvta_generic_to_shared(smh);

    const int tid  = threadIdx.x;
    const int lane = tid & 31;
    const int wid  = tid >> 5;
    const int wm   = wid >> 2;      // 0..3
    const int wn   = wid & 3;       // 0..3
    const int g    = lane >> 2;
    const int c    = lane & 3;
    const int skew = wid & 3;

    const int nk = I_HALF / BKH;    // 86

    uint32_t a_off[4], b_off[2];
    {
        const int ar = wm * 64 + ((lane >> 3) & 1) * 8 + (lane & 7);
        const int ac = ((lane >> 4) & 1) * 8;
#pragma unroll
        for (int i = 0; i < 4; ++i) a_off[i] = (uint32_t)((ar + i * 16) * LDSTR + ac);
        const int br = wn * 32 + ((lane >> 4) & 1) * 8 + (lane & 7);
        const int bc = ((lane >> 3) & 1) * 8;
#pragma unroll
        for (int p = 0; p < 2; ++p)
            b_off[p] = (uint32_t)(TILE256 + (br + p * 16) * LDSTR + bc);
    }

    const __half* srcA = g_h  + (size_t)m0 * I_DIM + k_base;
    const __half* srcB = g_wd + (size_t)n0 * I_DIM + k_base;

#define ISSUE_D(t) do {                                                        \
        __half* st = smh + ((t) % S) * STG_D;                                  \
        const size_t kof = (size_t)(t) * BKH;                                  \
        _Pragma("unroll")                                                      \
        for (int ii = 0; ii < 4; ++ii) {                                       \
            int id = tid + ii * 512;                                           \
            int row = id >> 3, ch = id & 7;                                    \
            cp16(st + row * LDSTR + ch * 8,                                    \
                 srcA + (size_t)row * I_DIM + kof + ch * 8);                   \
        }                                                                      \
        _Pragma("unroll")                                                      \
        for (int ii = 0; ii < 2; ++ii) {                                       \
            int id = tid + ii * 512;                                           \
            int row = id >> 3, ch = id & 7;                                    \
            cp16(st + TILE256 + row * LDSTR + ch * 8,                          \
                 srcB + (size_t)row * I_DIM + kof + ch * 8);                   \
        }                                                                      \
    } while (0)

#pragma unroll
    for (int t = 0; t < S - 1; ++t) { ISSUE_D(t); CP_COMMIT(); }

    float acc[4][4][4];
#pragma unroll
    for (int i = 0; i < 4; ++i)
#pragma unroll
        for (int j = 0; j < 4; ++j)
#pragma unroll
            for (int r = 0; r < 4; ++r) acc[i][j][r] = 0.f;

    for (int t = 0; t < nk; ++t) {
        CP_WAIT(S - 2);
        __syncthreads();
        if (t + S - 1 < nk) ISSUE_D(t + S - 1);
        CP_COMMIT();

        const uint32_t sb = smem_b + (uint32_t)((t % S) * STG_D) * 2;

#pragma unroll
        for (int kgi = 0; kgi < 4; ++kgi) {
            const int kg = (kgi + skew) & 3;
            const uint32_t kb = (uint32_t)kg * 32;
            uint32_t af[4][4], bf[4][2];
#pragma unroll
            for (int i = 0; i < 4; ++i) ldsm4(sb + 2 * a_off[i] + kb, af[i]);
#pragma unroll
            for (int p = 0; p < 2; ++p) {
                uint32_t rb[4];
                ldsm4(sb + 2 * b_off[p] + kb, rb);
                bf[2 * p][0] = rb[0]; bf[2 * p][1] = rb[1];
                bf[2 * p + 1][0] = rb[2]; bf[2 * p + 1][1] = rb[3];
            }
#pragma unroll
            for (int i = 0; i < 4; ++i)
#pragma unroll
                for (int j = 0; j < 4; ++j)
                    mma16(acc[i][j], af[i], bf[j]);
        }
    }
#undef ISSUE_D

    // epilogue: scatter (write or accumulate)
#pragma unroll
    for (int i = 0; i < 4; ++i) {
#pragma unroll
        for (int h = 0; h < 2; ++h) {
            const int gm = m0 + wm * 64 + i * 16 + g + h * 8;
            if (gm < Mc) {
                float* rowp = out + (size_t)g_idx[gm] * H_DIM;
#pragma unroll
                for (int j = 0; j < 4; ++j) {
                    const int gn = n0 + wn * 32 + j * 8 + c * 2;
                    float2 v = make_float2(acc[i][j][h * 2 + 0], acc[i][j][h * 2 + 1]);
                    if (ACC) {
                        float2 prev = *(float2*)(rowp + gn);
                        v.x += prev.x; v.y += prev.y;
                    }
                    *(float2*)(rowp + gn) = v;
                }
            }
        }
    }
}

// ---------------------------------------------------------------------------
extern "C" void kernel_launch(void* const* d_in, const int* in_sizes, int n_in,
                              void* d_out, int out_size)
{
    const float* hidden = (const float*)d_in[0];
    const float* w_up   = (const float*)d_in[1];
    const float* w_gate = (const float*)d_in[2];
    const float* w_down = (const float*)d_in[3];
    const int*   mask   = (const int*)d_in[4];
    float* out = (float*)d_out;

    const int SMEM_F = S * STG_F * sizeof(__half);   // 221184
    const int SMEM_D = S * STG_D * sizeof(__half);   // 221184
    cudaFuncSetAttribute(fused_upgate_kernel, cudaFuncAttributeMaxDynamicSharedMemorySize, SMEM_F);
    cudaFuncSetAttribute(down_kernel<0>,      cudaFuncAttributeMaxDynamicSharedMemorySize, SMEM_D);
    cudaFuncSetAttribute(down_kernel<1>,      cudaFuncAttributeMaxDynamicSharedMemorySize, SMEM_D);

    void *d_wu, *d_wg, *d_wd;
    cudaGetSymbolAddress(&d_wu, g_wu);
    cudaGetSymbolAddress(&d_wg, g_wg);
    cudaGetSymbolAddress(&d_wd, g_wd);

    const int half_groups = (I_HALF * H_DIM) / 8;          // groups of 8 floats
    const size_t half_floats = (size_t)I_HALF * H_DIM;
    const int wd_groups = (I_DIM * H_DIM) / 8;

    // ---- main: compact, then fork side stream ----
    compact_kernel<<<1, 1024>>>(mask);
    cudaEventRecord(g_aux.ev_fork, 0);
    cudaStreamWaitEvent(g_aux.side, g_aux.ev_fork, 0);

    // ---- side: staged weight conversion + zero + down_k0 ----
    cvt_kernel<<<2048, 256, 0, g_aux.side>>>((const float4*)w_up,   (uint4*)d_wu, half_groups);
    cvt_kernel<<<2048, 256, 0, g_aux.side>>>((const float4*)w_gate, (uint4*)d_wg, half_groups);
    cudaEventRecord(g_aux.ev_A, g_aux.side);
    cvt_kernel<<<2048, 256, 0, g_aux.side>>>((const float4*)(w_up + half_floats),
                                             (uint4*)((__half*)d_wu + half_floats), half_groups);
    cvt_kernel<<<2048, 256, 0, g_aux.side>>>((const float4*)(w_gate + half_floats),
                                             (uint4*)((__half*)d_wg + half_floats), half_groups);
    cudaEventRecord(g_aux.ev_B, g_aux.side);
    cvt_kernel<<<4096, 256, 0, g_aux.side>>>((const float4*)w_down, (uint4*)d_wd, wd_groups);
    zero_rows_kernel<<<NTOK, 256, 0, g_aux.side>>>((float4*)out);

    // ---- main: gather, fused n-half0 (gated on first cvt half) ----
    gather_kernel<<<NTOK, 256>>>((const float4*)hidden);

    dim3 blk(NTHREADS);
    cudaStreamWaitEvent(0, g_aux.ev_A, 0);
    fused_upgate_kernel<<<dim3(NTOK / 128, I_HALF / 128), blk, SMEM_F>>>(0);
    cudaEventRecord(g_aux.ev_F0, 0);

    // side: down_k0 (needs g_h[:, 0:I_HALF) = fused n-half0, plus wd cvt + zero done)
    cudaStreamWaitEvent(g_aux.side, g_aux.ev_F0, 0);
    down_kernel<0><<<dim3(NTOK / 256, H_DIM / 128), blk, SMEM_D, g_aux.side>>>(out, 0);
    cudaEventRecord(g_aux.ev_S, g_aux.side);

    // main: fused n-half1 (overlaps down_k0), then down_k1 accumulates
    cudaStreamWaitEvent(0, g_aux.ev_B, 0);
    fused_upgate_kernel<<<dim3(NTOK / 128, I_HALF / 128), blk, SMEM_F>>>(I_HALF / 128);
    cudaStreamWaitEvent(0, g_aux.ev_S, 0);
    down_kernel<1><<<dim3(NTOK / 256, H_DIM / 128), blk, SMEM_D>>>(out, I_HALF);
}

// round 15
// speedup vs baseline: 1.0663x; 1.0010x over previous
#include <cuda_runtime.h>
#include <cuda_fp16.h>
#include <cstdint>
#include <math.h>

// Problem dims (fixed)
#define H_DIM 4096
#define I_DIM 11008
#define NTOK  4096

#define BKH 64                          // halves (k) per pipeline stage
#define S  4
#define LDSTR 72                        // halves per smem row (128B data + 16B pad)
#define TILE128 (128 * LDSTR)
#define TILE256 (256 * LDSTR)
#define NTHREADS 512

// n-quarter boundaries in 128-blocks: sizes 22,22,21,21 (sum 86)
__host__ __device__ __forceinline__ int qb(int q) {
    const int t[5] = {0, 22, 44, 65, 86};
    return t[q];
}

// Device scratch — natural K-major fp16 layouts
__device__ __half g_x[(size_t)NTOK * H_DIM];
__device__ __half g_h[(size_t)NTOK * I_DIM];
__device__ __half g_wu[(size_t)I_DIM * H_DIM];
__device__ __half g_wg[(size_t)I_DIM * H_DIM];
__device__ __half g_wd[(size_t)H_DIM * I_DIM];
__device__ int    g_idx[NTOK];
__device__ int    g_zidx[NTOK];
__device__ int    g_count;

// ---------------------------------------------------------------------------
// Side stream + events (host-side only, created once at static init)
// ---------------------------------------------------------------------------
struct AuxStreams {
    cudaStream_t side;
    cudaEvent_t ev_fork, ev_C[4], ev_F[3], ev_S;
    AuxStreams() {
        cudaStreamCreateWithFlags(&side, cudaStreamNonBlocking);
        cudaEventCreateWithFlags(&ev_fork, cudaEventDisableTiming);
        for (int i = 0; i < 4; ++i) cudaEventCreateWithFlags(&ev_C[i], cudaEventDisableTiming);
        for (int i = 0; i < 3; ++i) cudaEventCreateWithFlags(&ev_F[i], cudaEventDisableTiming);
        cudaEventCreateWithFlags(&ev_S, cudaEventDisableTiming);
    }
};
static AuxStreams g_aux;

// ---------------------------------------------------------------------------
__device__ __forceinline__ uint32_t h2_as_u32(__half2 h) {
    return *reinterpret_cast<uint32_t*>(&h);
}
__device__ __forceinline__ void cp16(void* dst_smem, const void* src) {
    uint32_t d = (uint32_t)__cvta_generic_to_shared(dst_smem);
    asm volatile("cp.async.cg.shared.global [%0], [%1], 16;" :: "r"(d), "l"(src) : "memory");
}
#define CP_COMMIT() asm volatile("cp.async.commit_group;" ::: "memory")
#define CP_WAIT(n)  asm volatile("cp.async.wait_group %0;" :: "n"(n) : "memory")

__device__ __forceinline__ void mma16(float* d, const uint32_t* a, const uint32_t* b) {
    asm volatile(
        "mma.sync.aligned.m16n8k16.row.col.f32.f16.f16.f32 "
        "{%0,%1,%2,%3}, {%4,%5,%6,%7}, {%8,%9}, {%0,%1,%2,%3};"
        : "+f"(d[0]), "+f"(d[1]), "+f"(d[2]), "+f"(d[3])
        : "r"(a[0]), "r"(a[1]), "r"(a[2]), "r"(a[3]), "r"(b[0]), "r"(b[1]));
}
__device__ __forceinline__ void ldsm4(uint32_t addr, uint32_t* r) {
    asm volatile("ldmatrix.sync.aligned.m8n8.x4.shared.b16 {%0,%1,%2,%3}, [%4];"
                 : "=r"(r[0]), "=r"(r[1]), "=r"(r[2]), "=r"(r[3]) : "r"(addr));
}

// ---------------------------------------------------------------------------
// Compaction scan (single block): active list + inactive list
// ---------------------------------------------------------------------------
__global__ void compact_kernel(const int* __restrict__ mask) {
    __shared__ int warp_sums[32];
    const int tid = threadIdx.x, lane = tid & 31, warp = tid >> 5;
    int flags[4], cnt = 0;
#pragma unroll
    for (int j = 0; j < 4; ++j) {
        int f = (mask[tid * 4 + j] != 0) ? 1 : 0;
        flags[j] = f; cnt += f;
    }
    int v = cnt;
#pragma unroll
    for (int o = 1; o < 32; o <<= 1) { int n = __shfl_up_sync(~0u, v, o); if (lane >= o) v += n; }
    if (lane == 31) warp_sums[warp] = v;
    __syncthreads();
    if (warp == 0) {
        int s = warp_sums[lane];
#pragma unroll
        for (int o = 1; o < 32; o <<= 1) { int n = __shfl_up_sync(~0u, s, o); if (lane >= o) s += n; }
        warp_sums[lane] = s;
    }
    __syncthreads();
    int base = v - cnt + (warp > 0 ? warp_sums[warp - 1] : 0);
#pragma unroll
    for (int j = 0; j < 4; ++j) {
        int t = tid * 4 + j;
        if (flags[j]) g_idx[base++] = t;
        else          g_zidx[t - base] = t;
    }
    if (tid == 1023) g_count = base;
}

// ---------------------------------------------------------------------------
__device__ __forceinline__ uint4 cvt8(float4 f0, float4 f1) {
    uint4 o;
    o.x = h2_as_u32(__floats2half2_rn(f0.x, f0.y));
    o.y = h2_as_u32(__floats2half2_rn(f0.z, f0.w));
    o.z = h2_as_u32(__floats2half2_rn(f1.x, f1.y));
    o.w = h2_as_u32(__floats2half2_rn(f1.z, f1.w));
    return o;
}

__global__ void cvt_kernel(const float4* __restrict__ src, uint4* __restrict__ dst, int ngroups) {
    int i = blockIdx.x * blockDim.x + threadIdx.x;
    int stride = gridDim.x * blockDim.x;
    for (; i < ngroups; i += stride) dst[i] = cvt8(src[2 * i], src[2 * i + 1]);
}

// Gather active rows into g_x (fp16); zero-pad to 128-row boundary.
__global__ void gather_kernel(const float4* __restrict__ hidden) {
    int row = blockIdx.x;
    int c = g_count;
    int cpad = (c + 127) & ~127;
    if (row >= cpad) return;
    uint4* dst = (uint4*)(g_x + (size_t)row * H_DIM);
    if (row < c) {
        const float4* src = hidden + (size_t)g_idx[row] * (H_DIM / 4);
        for (int i = threadIdx.x; i < H_DIM / 8; i += 256)
            dst[i] = cvt8(src[2 * i], src[2 * i + 1]);
    } else {
        uint4 z = make_uint4(0, 0, 0, 0);
        for (int i = threadIdx.x; i < H_DIM / 8; i += 256) dst[i] = z;
    }
}

__global__ void zero_rows_kernel(float4* __restrict__ out) {
    int nz = NTOK - g_count;
    if ((int)blockIdx.x >= nz) return;
    float4* p = out + (size_t)g_zidx[blockIdx.x] * (H_DIM / 4);
    float4 z = make_float4(0.f, 0.f, 0.f, 0.f);
    for (int i = threadIdx.x; i < H_DIM / 4; i += 256) p[i] = z;
}

// ---------------------------------------------------------------------------
// Fused up+gate GEMM. Block 128x128, 16 warps @ 32x32 (4m x 4n), dual acc,
// per-warp kg skew. n_off selects the n-quarter (in 128-blocks).
// ---------------------------------------------------------------------------
#define STG_F (3 * TILE128)   // halves per stage

__global__ __launch_bounds__(NTHREADS, 1)
void fused_upgate_kernel(int n_off)
{
    const int Mc = g_count;
    const int m0 = blockIdx.x * 128;
    if (m0 >= Mc) return;
    const int n0 = (blockIdx.y + n_off) * 128;

    extern __shared__ __half smh[];
    const uint32_t smem_b = (uint32_t)__cvta_generic_to_shared(smh);

    const int tid  = threadIdx.x;
    const int lane = tid & 31;
    const int wid  = tid >> 5;      // 0..15
    const int wm   = wid >> 2;      // 0..3
    const int wn   = wid & 3;       // 0..3
    const int g    = lane >> 2;
    const int c    = lane & 3;
    const int skew = wid & 3;

    const int nk = H_DIM / BKH;     // 64

    uint32_t a_off[2], u_off[2], gg_off[2];
    {
        const int ar = wm * 32 + ((lane >> 3) & 1) * 8 + (lane & 7);
        const int ac = ((lane >> 4) & 1) * 8;
#pragma unroll
        for (int i = 0; i < 2; ++i) a_off[i] = (uint32_t)((ar + i * 16) * LDSTR + ac);
        const int br = wn * 32 + ((lane >> 4) & 1) * 8 + (lane & 7);
        const int bc = ((lane >> 3) & 1) * 8;
#pragma unroll
        for (int p = 0; p < 2; ++p) {
            u_off[p]  = (uint32_t)(TILE128     + (br + p * 16) * LDSTR + bc);
            gg_off[p] = (uint32_t)(2 * TILE128 + (br + p * 16) * LDSTR + bc);
        }
    }

    const __half* srcA = g_x  + (size_t)m0 * H_DIM;
    const __half* srcU = g_wu + (size_t)n0 * H_DIM;
    const __half* srcG = g_wg + (size_t)n0 * H_DIM;

#define ISSUE_F(t) do {                                                        \
        __half* st = smh + ((t) % S) * STG_F;                                  \
        const size_t kof = (size_t)(t) * BKH;                                  \
        _Pragma("unroll")                                                      \
        for (int ii = 0; ii < 2; ++ii) {                                       \
            int id = tid + ii * 512;                                           \
            int row = id >> 3, ch = id & 7;                                    \
            cp16(st + row * LDSTR + ch * 8,                                    \
                 srcA + (size_t)row * H_DIM + kof + ch * 8);                   \
            cp16(st + TILE128 + row * LDSTR + ch * 8,                          \
                 srcU + (size_t)row * H_DIM + kof + ch * 8);                   \
            cp16(st + 2 * TILE128 + row * LDSTR + ch * 8,                      \
                 srcG + (size_t)row * H_DIM + kof + ch * 8);                   \
        }                                                                      \
    } while (0)

#pragma unroll
    for (int t = 0; t < S - 1; ++t) { ISSUE_F(t); CP_COMMIT(); }

    float acc_u[2][4][4], acc_g[2][4][4];
#pragma unroll
    for (int i = 0; i < 2; ++i)
#pragma unroll
        for (int j = 0; j < 4; ++j)
#pragma unroll
            for (int r = 0; r < 4; ++r) { acc_u[i][j][r] = 0.f; acc_g[i][j][r] = 0.f; }

    for (int t = 0; t < nk; ++t) {
        CP_WAIT(S - 2);
        __syncthreads();
        if (t + S - 1 < nk) ISSUE_F(t + S - 1);
        CP_COMMIT();

        const uint32_t sb = smem_b + (uint32_t)((t % S) * STG_F) * 2;

#pragma unroll
        for (int kgi = 0; kgi < 4; ++kgi) {
            const int kg = (kgi + skew) & 3;
            const uint32_t kb = (uint32_t)kg * 32;
            uint32_t af[2][4], uf[4][2], gf[4][2];
#pragma unroll
            for (int i = 0; i < 2; ++i) ldsm4(sb + 2 * a_off[i] + kb, af[i]);
#pragma unroll
            for (int p = 0; p < 2; ++p) {
                uint32_t ru[4], rg[4];
                ldsm4(sb + 2 * u_off[p] + kb, ru);
                ldsm4(sb + 2 * gg_off[p] + kb, rg);
                uf[2 * p][0] = ru[0]; uf[2 * p][1] = ru[1];
                uf[2 * p + 1][0] = ru[2]; uf[2 * p + 1][1] = ru[3];
                gf[2 * p][0] = rg[0]; gf[2 * p][1] = rg[1];
                gf[2 * p + 1][0] = rg[2]; gf[2 * p + 1][1] = rg[3];
            }
#pragma unroll
            for (int i = 0; i < 2; ++i)
#pragma unroll
                for (int j = 0; j < 4; ++j) {
                    mma16(acc_u[i][j], af[i], uf[j]);
                    mma16(acc_g[i][j], af[i], gf[j]);
                }
        }
    }
#undef ISSUE_F

    // epilogue: h = up*silu(gate) -> fp16
#pragma unroll
    for (int i = 0; i < 2; ++i) {
#pragma unroll
        for (int h = 0; h < 2; ++h) {
            const int gm = m0 + wm * 32 + i * 16 + g + h * 8;
            __half* rowp = g_h + (size_t)gm * I_DIM;
#pragma unroll
            for (int j = 0; j < 4; ++j) {
                const int gn = n0 + wn * 32 + j * 8 + 2 * c;
                float u0 = acc_u[i][j][h * 2 + 0], u1 = acc_u[i][j][h * 2 + 1];
                float gg0 = acc_g[i][j][h * 2 + 0], gg1 = acc_g[i][j][h * 2 + 1];
                float h0 = u0 * (gg0 / (1.f + __expf(-gg0)));
                float h1 = u1 * (gg1 / (1.f + __expf(-gg1)));
                *(__half2*)(rowp + gn) = __floats2half2_rn(h0, h1);
            }
        }
    }
}

// ---------------------------------------------------------------------------
// Down GEMM, split-K. Block 256x128, 16 warps @ 64x32 (4m x 4n), kg skew.
// k_base/nk select the K chunk; ACC=0 writes out, ACC=1 accumulates.
// ---------------------------------------------------------------------------
#define STG_D (TILE256 + TILE128)

template <int ACC>
__global__ __launch_bounds__(NTHREADS, 1)
void down_kernel(float* __restrict__ out, int k_base, int nk)
{
    const int Mc = g_count;
    const int m0 = blockIdx.x * 256;
    if (m0 >= Mc) return;
    const int n0 = blockIdx.y * 128;

    extern __shared__ __half smh[];
    const uint32_t smem_b = (uint32_t)__cvta_generic_to_shared(smh);

    const int tid  = threadIdx.x;
    const int lane = tid & 31;
    const int wid  = tid >> 5;
    const int wm   = wid >> 2;      // 0..3
    const int wn   = wid & 3;       // 0..3
    const int g    = lane >> 2;
    const int c    = lane & 3;
    const int skew = wid & 3;

    uint32_t a_off[4], b_off[2];
    {
        const int ar = wm * 64 + ((lane >> 3) & 1) * 8 + (lane & 7);
        const int ac = ((lane >> 4) & 1) * 8;
#pragma unroll
        for (int i = 0; i < 4; ++i) a_off[i] = (uint32_t)((ar + i * 16) * LDSTR + ac);
        const int br = wn * 32 + ((lane >> 4) & 1) * 8 + (lane & 7);
        const int bc = ((lane >> 3) & 1) * 8;
#pragma unroll
        for (int p = 0; p < 2; ++p)
            b_off[p] = (uint32_t)(TILE256 + (br + p * 16) * LDSTR + bc);
    }

    const __half* srcA = g_h  + (size_t)m0 * I_DIM + k_base;
    const __half* srcB = g_wd + (size_t)n0 * I_DIM + k_base;

#define ISSUE_D(t) do {                                                        \
        __half* st = smh + ((t) % S) * STG_D;                                  \
        const size_t kof = (size_t)(t) * BKH;                                  \
        _Pragma("unroll")                                                      \
        for (int ii = 0; ii < 4; ++ii) {                                       \
            int id = tid + ii * 512;                                           \
            int row = id >> 3, ch = id & 7;                                    \
            cp16(st + row * LDSTR + ch * 8,                                    \
                 srcA + (size_t)row * I_DIM + kof + ch * 8);                   \
        }                                                                      \
        _Pragma("unroll")                                                      \
        for (int ii = 0; ii < 2; ++ii) {                                       \
            int id = tid + ii * 512;                                           \
            int row = id >> 3, ch = id & 7;                                    \
            cp16(st + TILE256 + row * LDSTR + ch * 8,                          \
                 srcB + (size_t)row * I_DIM + kof + ch * 8);                   \
        }                                                                      \
    } while (0)

#pragma unroll
    for (int t = 0; t < S - 1; ++t) { ISSUE_D(t); CP_COMMIT(); }

    float acc[4][4][4];
#pragma unroll
    for (int i = 0; i < 4; ++i)
#pragma unroll
        for (int j = 0; j < 4; ++j)
#pragma unroll
            for (int r = 0; r < 4; ++r) acc[i][j][r] = 0.f;

    for (int t = 0; t < nk; ++t) {
        CP_WAIT(S - 2);
        __syncthreads();
        if (t + S - 1 < nk) ISSUE_D(t + S - 1);
        CP_COMMIT();

        const uint32_t sb = smem_b + (uint32_t)((t % S) * STG_D) * 2;

#pragma unroll
        for (int kgi = 0; kgi < 4; ++kgi) {
            const int kg = (kgi + skew) & 3;
            const uint32_t kb = (uint32_t)kg * 32;
            uint32_t af[4][4], bf[4][2];
#pragma unroll
            for (int i = 0; i < 4; ++i) ldsm4(sb + 2 * a_off[i] + kb, af[i]);
#pragma unroll
            for (int p = 0; p < 2; ++p) {
                uint32_t rb[4];
                ldsm4(sb + 2 * b_off[p] + kb, rb);
                bf[2 * p][0] = rb[0]; bf[2 * p][1] = rb[1];
                bf[2 * p + 1][0] = rb[2]; bf[2 * p + 1][1] = rb[3];
            }
#pragma unroll
            for (int i = 0; i < 4; ++i)
#pragma unroll
                for (int j = 0; j < 4; ++j)
                    mma16(acc[i][j], af[i], bf[j]);
        }
    }
#undef ISSUE_D

    // epilogue: scatter (write or accumulate)
#pragma unroll
    for (int i = 0; i < 4; ++i) {
#pragma unroll
        for (int h = 0; h < 2; ++h) {
            const int gm = m0 + wm * 64 + i * 16 + g + h * 8;
            if (gm < Mc) {
                float* rowp = out + (size_t)g_idx[gm] * H_DIM;
#pragma unroll
                for (int j = 0; j < 4; ++j) {
                    const int gn = n0 + wn * 32 + j * 8 + c * 2;
                    float2 v = make_float2(acc[i][j][h * 2 + 0], acc[i][j][h * 2 + 1]);
                    if (ACC) {
                        float2 prev = *(float2*)(rowp + gn);
                        v.x += prev.x; v.y += prev.y;
                    }
                    *(float2*)(rowp + gn) = v;
                }
            }
        }
    }
}

// ---------------------------------------------------------------------------
extern "C" void kernel_launch(void* const* d_in, const int* in_sizes, int n_in,
                              void* d_out, int out_size)
{
    const float* hidden = (const float*)d_in[0];
    const float* w_up   = (const float*)d_in[1];
    const float* w_gate = (const float*)d_in[2];
    const float* w_down = (const float*)d_in[3];
    const int*   mask   = (const int*)d_in[4];
    float* out = (float*)d_out;

    const int SMEM_F = S * STG_F * sizeof(__half);   // 221184
    const int SMEM_D = S * STG_D * sizeof(__half);   // 221184
    cudaFuncSetAttribute(fused_upgate_kernel, cudaFuncAttributeMaxDynamicSharedMemorySize, SMEM_F);
    cudaFuncSetAttribute(down_kernel<0>,      cudaFuncAttributeMaxDynamicSharedMemorySize, SMEM_D);
    cudaFuncSetAttribute(down_kernel<1>,      cudaFuncAttributeMaxDynamicSharedMemorySize, SMEM_D);

    void *d_wu, *d_wg, *d_wd;
    cudaGetSymbolAddress(&d_wu, g_wu);
    cudaGetSymbolAddress(&d_wg, g_wg);
    cudaGetSymbolAddress(&d_wd, g_wd);

    const int wd_groups = (I_DIM * H_DIM) / 8;

    // ---- main: compact, then fork side stream ----
    compact_kernel<<<1, 1024>>>(mask);
    cudaEventRecord(g_aux.ev_fork, 0);
    cudaStreamWaitEvent(g_aux.side, g_aux.ev_fork, 0);

    // ---- side: quarter-staged weight conversion ----
    for (int q = 0; q < 4; ++q) {
        const size_t row0 = (size_t)qb(q) * 128;
        const size_t rows = (size_t)(qb(q + 1) - qb(q)) * 128;
        const size_t f_off = row0 * H_DIM;
        const int groups = (int)(rows * H_DIM / 8);
        cvt_kernel<<<2048, 256, 0, g_aux.side>>>(
            (const float4*)(w_up + f_off), (uint4*)((__half*)d_wu + f_off), groups);
        cvt_kernel<<<2048, 256, 0, g_aux.side>>>(
            (const float4*)(w_gate + f_off), (uint4*)((__half*)d_wg + f_off), groups);
        cudaEventRecord(g_aux.ev_C[q], g_aux.side);
    }
    cvt_kernel<<<4096, 256, 0, g_aux.side>>>((const float4*)w_down, (uint4*)d_wd, wd_groups);
    zero_rows_kernel<<<NTOK, 256, 0, g_aux.side>>>((float4*)out);

    // ---- main: gather, then fused quarters gated on cvt quarters ----
    gather_kernel<<<NTOK, 256>>>((const float4*)hidden);

    dim3 blk(NTHREADS);
    for (int q = 0; q < 4; ++q) {
        cudaStreamWaitEvent(0, g_aux.ev_C[q], 0);
        fused_upgate_kernel<<<dim3(NTOK / 128, qb(q + 1) - qb(q)), blk, SMEM_F>>>(qb(q));
        if (q < 3) cudaEventRecord(g_aux.ev_F[q], 0);
    }

    // ---- side: down chunks 0..2 overlap fused quarters 1..3 ----
    for (int q = 0; q < 3; ++q) {
        cudaStreamWaitEvent(g_aux.side, g_aux.ev_F[q], 0);
        const int k_base = qb(q) * 128;
        const int nk = (qb(q + 1) - qb(q)) * 2;   // *128/64
        if (q == 0)
            down_kernel<0><<<dim3(NTOK / 256, H_DIM / 128), blk, SMEM_D, g_aux.side>>>(out, k_base, nk);
        else
            down_kernel<1><<<dim3(NTOK / 256, H_DIM / 128), blk, SMEM_D, g_aux.side>>>(out, k_base, nk);
    }
    cudaEventRecord(g_aux.ev_S, g_aux.side);

    // ---- main: final down chunk (accumulate) after last fused + side joins ----
    cudaStreamWaitEvent(0, g_aux.ev_S, 0);
    down_kernel<1><<<dim3(NTOK / 256, H_DIM / 128), blk, SMEM_D>>>(out, qb(3) * 128, (qb(4) - qb(3)) * 2);
}